// round 17
// baseline (speedup 1.0000x reference)
#include <cuda_runtime.h>

// LossFunction: fused IoU + smooth-L1 multi-loss over (B=256, N=8192, F=13).
//
// R17 = R3's champion body (256 thr, 1024-row tile, 13x unrolled coalesced
// LDG.128 pairs, per-element weight + predicated STS.32 box staging, smem
// IoU pass) — empirically the fastest traffic-optimal structure (5.37 TB/s,
// 41.3us kernel; every restructure in R10-R16 degraded the rate) — with the
// separate init launch + atomic tail replaced by an in-kernel ticket +
// last-block deterministic reduction (saves the ~2us launch gap).

#define F 13
#define ROWS_PER_BLOCK 1024
#define THREADS 256
#define MAX_BLOCKS 4096

__device__ float        g_partials[MAX_BLOCKS];
__device__ unsigned int g_ticket = 0;

__device__ __forceinline__ float huber(float a, float b) {
    float d = fabsf(a - b);
    return d < 1.0f ? 0.5f * d * d : d - 0.5f;
}

__global__ __launch_bounds__(THREADS)
void loss_kernel(const float* __restrict__ tg,
                 const float* __restrict__ pr,
                 float* __restrict__ out,
                 long long rows,
                 float c1, float c2, float c3, float c4) {
    // Box features only: 4 floats per row per tensor (32KB total).
    __shared__ float st_box[ROWS_PER_BLOCK * 4];
    __shared__ float sp_box[ROWS_PER_BLOCK * 4];
    __shared__ float warp_part[THREADS / 32];
    __shared__ bool  is_last;

    long long row0 = (long long)blockIdx.x * ROWS_PER_BLOCK;
    long long rem  = rows - row0;
    int nrows = rem < ROWS_PER_BLOCK ? (int)rem : ROWS_PER_BLOCK;

    const float* tbase = tg + row0 * F;
    const float* pbase = pr + row0 * F;

    float acc = 0.0f;

    if (nrows == ROWS_PER_BLOCK) {
        const float4* t4 = (const float4*)tbase;
        const float4* p4 = (const float4*)pbase;
        const int NF4 = ROWS_PER_BLOCK * F / 4;  // 3328 = 13 * THREADS
        #pragma unroll 13
        for (int i = threadIdx.x; i < NF4; i += THREADS) {
            float4 t = t4[i];
            float4 p = p4[i];
            int g = 4 * i;
            float tv[4] = {t.x, t.y, t.z, t.w};
            float pv[4] = {p.x, p.y, p.z, p.w};
            #pragma unroll
            for (int j = 0; j < 4; j++) {
                int gg  = g + j;
                int row = gg / F;            // const-div -> magic multiply
                int f   = gg - row * F;
                float wgt = (f < 4) ? c2 : ((f < 12) ? c4 : c3);
                acc += wgt * huber(tv[j], pv[j]);
                if (f < 4) {
                    st_box[row * 4 + f] = tv[j];
                    sp_box[row * 4 + f] = pv[j];
                }
            }
        }
    } else {
        // tail block (not hit for the benchmark shape)
        int nflt = nrows * F;
        for (int gg = threadIdx.x; gg < nflt; gg += THREADS) {
            float tv = tbase[gg];
            float pv = pbase[gg];
            int row = gg / F;
            int f   = gg - row * F;
            float wgt = (f < 4) ? c2 : ((f < 12) ? c4 : c3);
            acc += wgt * huber(tv, pv);
            if (f < 4) {
                st_box[row * 4 + f] = tv;
                sp_box[row * 4 + f] = pv;
            }
        }
    }
    __syncthreads();

    // IoU loss: one conflict-free LDS.128 per row per tensor.
    for (int r = threadIdx.x; r < nrows; r += THREADS) {
        float4 tb = *(const float4*)&st_box[r * 4];
        float4 pb = *(const float4*)&sp_box[r * 4];
        float xx1 = fmaxf(tb.x, pb.x);
        float yy1 = fmaxf(tb.y, pb.y);
        float xx2 = fminf(tb.z, pb.z);
        float yy2 = fminf(tb.w, pb.w);
        float w = fmaxf(xx2 - xx1, 0.0f);
        float h = fmaxf(yy2 - yy1, 0.0f);
        float inter = w * h;
        float area1 = (tb.z - tb.x) * (tb.w - tb.y);
        float area2 = (pb.z - pb.x) * (pb.w - pb.y);
        float iou = inter / (area1 + area2 - inter + 1e-7f);
        acc += c1 * huber(1.0f, iou);
    }

    // ---- Block reduction ----
    #pragma unroll
    for (int off = 16; off > 0; off >>= 1)
        acc += __shfl_xor_sync(0xFFFFFFFFu, acc, off);

    int lane = threadIdx.x & 31;
    int wid  = threadIdx.x >> 5;
    if (lane == 0) warp_part[wid] = acc;
    __syncthreads();

    if (wid == 0) {
        float v = lane < (THREADS / 32) ? warp_part[lane] : 0.0f;
        #pragma unroll
        for (int off = 4; off > 0; off >>= 1)
            v += __shfl_xor_sync(0xFFFFFFFFu, v, off);
        if (lane == 0) {
            g_partials[blockIdx.x] = v;
            __threadfence();
            unsigned tk = atomicAdd(&g_ticket, 1u);
            is_last = (tk == gridDim.x - 1);
        }
    }
    __syncthreads();

    // Last block reduces all partials (deterministic order) and writes out.
    if (is_last) {
        __threadfence();
        float v = 0.0f;
        for (int i = threadIdx.x; i < (int)gridDim.x; i += THREADS)
            v += g_partials[i];
        #pragma unroll
        for (int off = 16; off > 0; off >>= 1)
            v += __shfl_xor_sync(0xFFFFFFFFu, v, off);
        if (lane == 0) warp_part[wid] = v;
        __syncthreads();
        if (wid == 0) {
            float s = lane < (THREADS / 32) ? warp_part[lane] : 0.0f;
            #pragma unroll
            for (int off = 4; off > 0; off >>= 1)
                s += __shfl_xor_sync(0xFFFFFFFFu, s, off);
            if (lane == 0) {
                out[0] = s;
                g_ticket = 0;   // reset for next graph replay
            }
        }
    }
}

extern "C" void kernel_launch(void* const* d_in, const int* in_sizes, int n_in,
                              void* d_out, int out_size) {
    const float* targets = (const float*)d_in[0];
    const float* preds   = (const float*)d_in[1];
    float* out = (float*)d_out;

    long long total = (long long)in_sizes[0];
    long long rows  = total / F;  // B*N = 2,097,152

    float inv = 1.0f / (float)rows;
    float c1 = inv;                 // loss1: mean over B*N
    float c2 = inv * 0.25f;         // loss2: mean over B*N*4
    float c3 = inv;                 // loss3: mean over B*N
    float c4 = 0.5f * inv * 0.125f; // loss4 * 0.5: mean over B*N*8

    int grid = (int)((rows + ROWS_PER_BLOCK - 1) / ROWS_PER_BLOCK);  // 2048
    if (grid > MAX_BLOCKS) grid = MAX_BLOCKS;  // safety (not hit for bench shape)

    loss_kernel<<<grid, THREADS>>>(targets, preds, out, rows, c1, c2, c3, c4);
}